// round 6
// baseline (speedup 1.0000x reference)
#include <cuda_runtime.h>
#include <cuda_bf16.h>
#include <cstdint>

// Problem constants (fixed by the reference generator).
#define NN   4096      // nodes
#define BB   2048      // batch
#define LL   128       // latent
#define KK   16        // max fan-in
#define DW   145       // 1 + LL + KK  (weights row length)
#define GKK  129       // 1 + LL       (GEMM K dim)

#define NE      14     // batch elements per CTA (147 CTAs -> single wave on 148 SMs)
#define STRIDE  4097   // per-element smem stride: bank = (el + p) mod 32

// ---------------------------------------------------------------------------
// Scratch (__device__ globals zero-initialized at load; padded tail rows are
// never written, so prefetch overruns read zeros).
// ---------------------------------------------------------------------------
__device__ float        g_pre[(NN + 8) * BB];     // pre[i*BB+b]
__device__ unsigned int g_meta[(NN + 8) * 32];    // per node: 16 parent idx + 16 w bits (128B)
__device__ float        g_wprev[NN + 8];          // sum of w over slots with parent==i-1

// ---------------------------------------------------------------------------
// Kernel 1: pack per-node metadata (one 128B line per node) + wprev.
// ---------------------------------------------------------------------------
__global__ void pack_meta_kernel(const float* __restrict__ w,
                                 const int*   __restrict__ par)
{
    const int wid = threadIdx.x >> 5;
    const int k   = threadIdx.x & 31;
    const int i   = blockIdx.x * 8 + wid;
    if (i >= NN) return;

    unsigned int v;
    float pw = 0.0f;
    if (k < 16) {
        int p = par[i * KK + k];
        v = (unsigned int)p;
        float wk = w[i * DW + (1 + LL) + k];
        pw = (p == i - 1) ? wk : 0.0f;
    } else {
        v = __float_as_uint(w[i * DW + (1 + LL) + (k - 16)]);
    }
    g_meta[i * 32 + k] = v;

    #pragma unroll
    for (int off = 8; off > 0; off >>= 1)
        pw += __shfl_down_sync(0xffffffffu, pw, off);
    if (k == 0) g_wprev[i] = pw;
}

// ---------------------------------------------------------------------------
// Kernel 2: pre[i][b] = sum_{k=0}^{128} w[i][k] * base[b][k],  base=[1, z].
// 64x64 tile, 256 threads, 4x4 register blocking, full K in smem.
// ---------------------------------------------------------------------------
#define G_PAD 68
__global__ void gemm_pre_kernel(const float* __restrict__ z,
                                const float* __restrict__ w)
{
    extern __shared__ float smg[];
    float* As = smg;
    float* Zs = smg + GKK * G_PAD;

    const int i0 = blockIdx.y * 64;
    const int b0 = blockIdx.x * 64;
    const int tid = threadIdx.x;

    for (int idx = tid; idx < 64 * GKK; idx += 256) {
        int r = idx / GKK, k = idx - r * GKK;
        As[k * G_PAD + r] = w[(i0 + r) * DW + k];
    }
    for (int idx = tid; idx < 64 * GKK; idx += 256) {
        int c = idx / GKK, k = idx - c * GKK;
        Zs[k * G_PAD + c] = (k == 0) ? 1.0f : z[(b0 + c) * LL + (k - 1)];
    }
    __syncthreads();

    const int tx = tid & 15;
    const int ty = tid >> 4;
    const int ri = ty * 4, ci = tx * 4;

    float acc[4][4];
#pragma unroll
    for (int r = 0; r < 4; r++)
#pragma unroll
        for (int c = 0; c < 4; c++) acc[r][c] = 0.0f;

#pragma unroll 3
    for (int k = 0; k < GKK; k++) {
        float4 a  = *reinterpret_cast<const float4*>(&As[k * G_PAD + ri]);
        float4 zc = *reinterpret_cast<const float4*>(&Zs[k * G_PAD + ci]);
        float av[4] = {a.x, a.y, a.z, a.w};
        float zv[4] = {zc.x, zc.y, zc.z, zc.w};
#pragma unroll
        for (int r = 0; r < 4; r++)
#pragma unroll
            for (int c = 0; c < 4; c++)
                acc[r][c] = fmaf(av[r], zv[c], acc[r][c]);
    }

#pragma unroll
    for (int r = 0; r < 4; r++) {
        float4 o = make_float4(acc[r][0], acc[r][1], acc[r][2], acc[r][3]);
        *reinterpret_cast<float4*>(&g_pre[(size_t)(i0 + ri + r) * BB + b0 + ci]) = o;
    }
}

// ---------------------------------------------------------------------------
// Kernel 3: sequential DAG chain, SPLIT-HALF-WARP version.
//   lanes 0-15 : parents 0-7  of element (lane&15, clamped to 13)
//   lanes 16-31: parents 8-15 of the same element
// Each half gathers 8 parents (8 LDS/warp/node instead of 16), computes its
// partial dot, and the halves are combined with one shfl_down(16).
// Stale-read trick: gathers for node m+1 are issued BEFORE u[m] is stored;
// a (parent==m) slot reads a deterministic 0 and is patched next iteration
// via s += t_prev * wprev. Meta/pre prefetched 4 nodes deep.
// ---------------------------------------------------------------------------
__global__ void __launch_bounds__(128, 1)
chain_kernel(float* __restrict__ out)
{
    extern __shared__ float sm[];
    const int tid = threadIdx.x;

    for (int j = tid; j < NE * STRIDE; j += 128) sm[j] = 0.0f;
    __syncthreads();

    if (tid < 32) {
        const int lane = tid;
        const int el_r = lane & 15;
        const int el   = el_r > 13 ? 13 : el_r;      // lanes 14,15,30,31 duplicate el 13 (broadcast, never store)
        const bool store_ok = (lane < 14);
        int b = blockIdx.x * NE + el;
        if (b >= BB) b = BB - 1;                     // duplicate work, dump-skipped
        float* __restrict__ u = sm + el * STRIDE;

        // Per-lane meta base: node*128 + half*32 bytes.
        const char* mb = reinterpret_cast<const char*>(g_meta) + ((lane >> 4) << 5);

        int4   P0[4], P1[4];
        float4 W0[4], W1[4];
        float  preb[4], wpb[4];
        float  g[8];

#pragma unroll
        for (int j = 0; j < 4; j++) {
            const char* pm = mb + (size_t)j * 128;
            P0[j] = __ldg(reinterpret_cast<const int4*>(pm));
            P1[j] = __ldg(reinterpret_cast<const int4*>(pm + 16));
            W0[j] = __ldg(reinterpret_cast<const float4*>(pm + 64));
            W1[j] = __ldg(reinterpret_cast<const float4*>(pm + 80));
            preb[j] = __ldg(g_pre + (size_t)j * BB + b);
            wpb[j]  = __ldg(g_wprev + j);
        }
#pragma unroll
        for (int k = 0; k < 8; k++) g[k] = 0.0f;     // node 0 has no live parents

        float tprev = 0.0f;

#pragma unroll 1
        for (int base = 0; base < NN; base += 4) {
#pragma unroll
            for (int j = 0; j < 4; j++) {
                const int m = base + j;

                // 1. partial dot over this half's 8 parents
                float a0 = g[0] * W0[j].x;
                float a1 = g[1] * W0[j].y;
                float a2 = g[2] * W0[j].z;
                float a3 = g[3] * W0[j].w;
                a0 = fmaf(g[4], W1[j].x, a0);
                a1 = fmaf(g[5], W1[j].y, a1);
                a2 = fmaf(g[6], W1[j].z, a2);
                a3 = fmaf(g[7], W1[j].w, a3);
                float part = (a0 + a1) + (a2 + a3);

                // 2. gathers for node m+1 (issued before u[m] store; a
                //    parent==m slot reads 0, patched via wprev next iter)
                {
                    const int jn = (j + 1) & 3;
                    int4 p0 = P0[jn], p1 = P1[jn];
                    g[0] = u[p0.x]; g[1] = u[p0.y]; g[2] = u[p0.z]; g[3] = u[p0.w];
                    g[4] = u[p1.x]; g[5] = u[p1.y]; g[6] = u[p1.z]; g[7] = u[p1.w];
                }

                // 3. combine halves + pre + wprev patch (valid on lanes 0-13)
                float oth = __shfl_down_sync(0xffffffffu, part, 16);
                float s = (part + oth) + preb[j];
                s = fmaf(tprev, wpb[j], s);

                // 4. tanh(s) = 1 - 2/(exp(2s)+1); exact at saturation
                float e, r;
                asm("ex2.approx.f32 %0, %1;" : "=f"(e) : "f"(s * 2.885390082f));
                asm("rcp.approx.f32 %0, %1;" : "=f"(r) : "f"(e + 1.0f));
                float t = fmaf(-2.0f, r, 1.0f);

                // 5. commit (lo lanes only; clamped/hi lanes never store)
                if (store_ok) u[m] = t;
                tprev = t;

                // 6. prefetch meta for node m+4 into slot j
                {
                    const char* pm = mb + (size_t)(m + 4) * 128;
                    P0[j] = __ldg(reinterpret_cast<const int4*>(pm));
                    P1[j] = __ldg(reinterpret_cast<const int4*>(pm + 16));
                    W0[j] = __ldg(reinterpret_cast<const float4*>(pm + 64));
                    W1[j] = __ldg(reinterpret_cast<const float4*>(pm + 80));
                    preb[j] = __ldg(g_pre + (size_t)(m + 4) * BB + b);
                    wpb[j]  = __ldg(g_wprev + m + 4);
                }
            }
        }
    }
    __syncthreads();

    // Cooperative coalesced dump: SMEM -> out[b*NN + i].
    for (int e = 0; e < NE; e++) {
        const int b = blockIdx.x * NE + e;
        if (b >= BB) break;
        const float* __restrict__ us = sm + e * STRIDE;
        for (int j = tid; j < NN; j += 128)
            out[(size_t)b * NN + j] = us[j];
    }
}

// ---------------------------------------------------------------------------
// Launch. Inputs: z f32[2048,128], weights f32[4096,145],
// parent_mask f32[4096,16] (redundant — weights pre-masked), parents i32[4096,16].
// Output: f32[2048, 4096].
// ---------------------------------------------------------------------------
extern "C" void kernel_launch(void* const* d_in, const int* in_sizes, int n_in,
                              void* d_out, int out_size)
{
    const float* z       = (const float*)d_in[0];
    const float* weights = (const float*)d_in[1];
    const int*   parents = (const int*)d_in[3];
    float*       out     = (float*)d_out;

    const int gemm_smem  = 2 * GKK * G_PAD * (int)sizeof(float);     // 70,176 B
    const int chain_smem = NE * STRIDE * (int)sizeof(float);         // 229,432 B

    cudaFuncSetAttribute(gemm_pre_kernel,
                         cudaFuncAttributeMaxDynamicSharedMemorySize, gemm_smem);
    cudaFuncSetAttribute(chain_kernel,
                         cudaFuncAttributeMaxDynamicSharedMemorySize, chain_smem);

    pack_meta_kernel<<<(NN + 7) / 8, 256>>>(weights, parents);

    dim3 ggrid(BB / 64, NN / 64);
    gemm_pre_kernel<<<ggrid, 256, gemm_smem>>>(z, weights);

    const int nblocks = (BB + NE - 1) / NE;   // 147
    chain_kernel<<<nblocks, 128, chain_smem>>>(out);
}